// round 1
// baseline (speedup 1.0000x reference)
#include <cuda_runtime.h>
#include <math.h>

// Problem constants (fixed by setup_inputs): x (2,3,384,384) f32, angles (2,180) f32
// Output sinogram (2,3,384,180) f32: out[b][c][i][k] = sum_j bilinear(x[b,c], rot_k(i,j))
#define BB 2
#define CC 3
#define HH 384
#define WW 384
#define KK 180

#define TI 32          // output tile in i (rows of sinogram / H axis)
#define TJ 32          // tile in j (summed axis)
#define NTI (HH / TI)  // 12
#define NTJ (WW / TJ)  // 12

#define BOX 48         // bounding box of a 32x32 rotated tile: 31*sqrt(2)+4 < 48
#define BSTR 49        // padded row stride in float4 (196 words % 32 == 4 -> bank rotate)

#define NTHREADS 256

// Partial sums: [b*K + k][i][jt][c]  (each element written exactly once)
__device__ float g_partial[BB * KK * HH * NTJ * CC];

__global__ __launch_bounds__(NTHREADS) void radon_tile_kernel(
    const float* __restrict__ x, const float* __restrict__ angles)
{
    __shared__ float4 sm[BOX * BSTR];

    const int bk = blockIdx.z;            // b*KK + k
    const int b  = bk / KK;
    const int ti = blockIdx.y;
    const int tj = blockIdx.x;
    const int i0 = ti * TI;
    const int j0 = tj * TJ;

    const float theta = angles[bk] * (float)(M_PI / 180.0);
    float s, c;
    sincosf(theta, &s, &c);

    // fx(i,j) = HC + (i-HC)*s + (j-HC)*c ; fy(i,j) = HC + (i-HC)*c - (j-HC)*s
    const float HC = 0.5f * (HH - 1);     // 191.5
    const float fx00 = HC + ((float)i0 - HC) * s + ((float)j0 - HC) * c;
    const float fy00 = HC + ((float)i0 - HC) * c - ((float)j0 - HC) * s;
    const float dix = s, djx = c;         // d(fx)/di, d(fx)/dj
    const float diy = c, djy = -s;        // d(fy)/di, d(fy)/dj

    // Affine over tile -> extremes at the 4 integer corners
    const float eI = (float)(TI - 1), eJ = (float)(TJ - 1);
    float fxA = fx00,             fxB = fx00 + eI * dix;
    float fxC = fx00 + eJ * djx,  fxD = fxB + eJ * djx;
    float fyA = fy00,             fyB = fy00 + eI * diy;
    float fyC = fy00 + eJ * djy,  fyD = fyB + eJ * djy;
    float fxmin = fminf(fminf(fxA, fxB), fminf(fxC, fxD));
    float fxmax = fmaxf(fmaxf(fxA, fxB), fmaxf(fxC, fxD));
    float fymin = fminf(fminf(fyA, fyB), fminf(fyC, fyD));
    float fymax = fmaxf(fmaxf(fyA, fyB), fmaxf(fyC, fyD));
    (void)fxmax; (void)fymax;

    const int xlo = (int)floorf(fxmin) - 1;   // 1-px guard on each side
    const int ylo = (int)floorf(fymin) - 1;

    // ---- Stage the 48x48 box (3 channels) into smem, zero-filled outside image ----
    const float* __restrict__ xb = x + (size_t)b * CC * HH * WW;
    #pragma unroll
    for (int p = threadIdx.x; p < BOX * BOX; p += NTHREADS) {
        const int by = p / BOX;
        const int bx = p - by * BOX;
        const int gy = ylo + by;
        const int gx = xlo + bx;
        float4 v = make_float4(0.f, 0.f, 0.f, 0.f);
        if ((unsigned)gy < (unsigned)HH && (unsigned)gx < (unsigned)WW) {
            const int o = gy * WW + gx;
            v.x = xb[o];
            v.y = xb[HH * WW + o];
            v.z = xb[2 * HH * WW + o];
        }
        sm[by * BSTR + bx] = v;
    }
    __syncthreads();

    // ---- Sample: thread t -> i_loc = t>>3, j in {t&7, +8, +16, +24} ----
    const int il = threadIdx.x >> 3;
    const int jb = threadIdx.x & 7;
    const float fx_i = fx00 + (float)il * dix;
    const float fy_i = fy00 + (float)il * diy;

    float s0 = 0.f, s1 = 0.f, s2 = 0.f;
    #pragma unroll
    for (int m = 0; m < 4; m++) {
        const float jl = (float)(jb + 8 * m);
        const float fx = fx_i + jl * djx;
        const float fy = fy_i + jl * djy;
        const float x0f = floorf(fx);
        const float y0f = floorf(fy);
        const float wx1 = fx - x0f, wx0 = 1.f - wx1;
        const float wy1 = fy - y0f, wy0 = 1.f - wy1;
        const int ix = (int)x0f - xlo;       // in [0, 46] by construction
        const int iy = (int)y0f - ylo;
        const float4* r0 = &sm[iy * BSTR + ix];
        const float4 p00 = r0[0];
        const float4 p01 = r0[1];
        const float4 p10 = r0[BSTR];
        const float4 p11 = r0[BSTR + 1];
        const float w00 = wy0 * wx0, w01 = wy0 * wx1;
        const float w10 = wy1 * wx0, w11 = wy1 * wx1;
        s0 += p00.x * w00 + p01.x * w01 + p10.x * w10 + p11.x * w11;
        s1 += p00.y * w00 + p01.y * w01 + p10.y * w10 + p11.y * w11;
        s2 += p00.z * w00 + p01.z * w01 + p10.z * w10 + p11.z * w11;
    }

    // Reduce across the 8 lanes sharing an i (width=8 keeps it inside the group)
    #pragma unroll
    for (int off = 4; off > 0; off >>= 1) {
        s0 += __shfl_down_sync(0xffffffffu, s0, off, 8);
        s1 += __shfl_down_sync(0xffffffffu, s1, off, 8);
        s2 += __shfl_down_sync(0xffffffffu, s2, off, 8);
    }
    if (jb == 0) {
        const int i = i0 + il;
        const int base = ((bk * HH + i) * NTJ + tj) * CC;
        g_partial[base + 0] = s0;
        g_partial[base + 1] = s1;
        g_partial[base + 2] = s2;
    }
}

__global__ __launch_bounds__(NTHREADS) void radon_reduce_kernel(float* __restrict__ out)
{
    const int o = blockIdx.x * NTHREADS + threadIdx.x;
    const int total = BB * CC * HH * KK;
    if (o >= total) return;
    const int k = o % KK;
    const int i = (o / KK) % HH;
    const int ch = (o / (KK * HH)) % CC;
    const int b = o / (KK * HH * CC);
    const float* __restrict__ p =
        &g_partial[(((b * KK + k) * HH + i) * NTJ) * CC + ch];
    float acc = 0.f;
    #pragma unroll
    for (int jt = 0; jt < NTJ; jt++) acc += p[jt * CC];
    out[o] = acc;
}

extern "C" void kernel_launch(void* const* d_in, const int* in_sizes, int n_in,
                              void* d_out, int out_size)
{
    const float* x = (const float*)d_in[0];       // (2,3,384,384)
    const float* angles = (const float*)d_in[1];  // (2,180)
    float* out = (float*)d_out;                   // (2,3,384,180)
    (void)in_sizes; (void)n_in; (void)out_size;

    dim3 grid1(NTJ, NTI, BB * KK);                // 12 x 12 x 360 = 51840 blocks
    radon_tile_kernel<<<grid1, NTHREADS>>>(x, angles);

    const int total = BB * CC * HH * KK;          // 414720
    radon_reduce_kernel<<<(total + NTHREADS - 1) / NTHREADS, NTHREADS>>>(out);
}

// round 2
// speedup vs baseline: 1.1480x; 1.1480x over previous
#include <cuda_runtime.h>
#include <math.h>

// x (2,3,384,384) f32, angles (2,180) f32 -> out (2,3,384,180) f32
// out[b][c][i][k] = sum_j bilinear(x[b,c], rot_k(i,j))
#define BB 2
#define CC 3
#define HH 384
#define WW 384
#define KK 180

#define TI 32
#define TJ 32
#define NTI (HH / TI)   // 12
#define NTJ (WW / TJ)   // 12

#define BOX 48          // bbox of 32x32 rotated tile + 1px guard each side
#define PSTR 49         // odd word stride -> bank-friendly column walks
#define PSZ (BOX * PSTR)

#define NTHREADS 256

__global__ __launch_bounds__(NTHREADS) void radon_fused_kernel(
    const float* __restrict__ x, const float* __restrict__ angles,
    float* __restrict__ out)
{
    __shared__ float sm[3 * PSZ];   // planar: ch0, ch1, ch2  (28.2 KB)

    const int ti = blockIdx.x;
    const int bk = blockIdx.y;        // b*KK + k
    const int b  = bk / KK;
    const int k  = bk - b * KK;
    const int i0 = ti * TI;

    const float theta = angles[bk] * (float)(M_PI / 180.0);
    float s, c;
    sincosf(theta, &s, &c);

    const float HC = 0.5f * (HH - 1);             // 191.5
    const float dix = s, djx = c;                  // d(fx)/di, d(fx)/dj
    const float diy = c, djy = -s;                 // d(fy)/di, d(fy)/dj

    const float* __restrict__ xb = x + (size_t)b * CC * HH * WW;
    const int HW = HH * WW;

    const int w = threadIdx.x >> 5;   // warp 0..7 -> i row within group
    const int l = threadIdx.x & 31;   // lane -> j within tile

    float acc[4][3];
    #pragma unroll
    for (int st = 0; st < 4; st++)
        #pragma unroll
        for (int ch = 0; ch < 3; ch++) acc[st][ch] = 0.f;

    for (int tj = 0; tj < NTJ; tj++) {
        const int j0 = tj * TJ;
        const float fx00 = HC + ((float)i0 - HC) * s + ((float)j0 - HC) * c;
        const float fy00 = HC + ((float)i0 - HC) * c - ((float)j0 - HC) * s;

        // tile is affine in (i,j): extremes at the 4 corners
        const float eI = (float)(TI - 1), eJ = (float)(TJ - 1);
        const float fxm = fminf(fminf(fx00, fx00 + eI * dix),
                                fminf(fx00 + eJ * djx, fx00 + eI * dix + eJ * djx));
        const float fym = fminf(fminf(fy00, fy00 + eI * diy),
                                fminf(fy00 + eJ * djy, fy00 + eI * diy + eJ * djy));
        const int xlo = (int)floorf(fxm) - 1;
        const int ylo = (int)floorf(fym) - 1;

        __syncthreads();   // previous tile's reads done before overwrite

        // ---- stage 48x48 box, planar, zero-filled outside image ----
        #pragma unroll
        for (int it = 0; it < (BOX * BOX) / NTHREADS; it++) {
            const int p  = threadIdx.x + it * NTHREADS;
            const int by = p / BOX;
            const int bx = p - by * BOX;
            const int gy = ylo + by;
            const int gx = xlo + bx;
            float v0 = 0.f, v1 = 0.f, v2 = 0.f;
            if ((unsigned)gy < (unsigned)HH && (unsigned)gx < (unsigned)WW) {
                const int o = gy * WW + gx;
                v0 = xb[o];
                v1 = xb[HW + o];
                v2 = xb[2 * HW + o];
            }
            const int si = by * PSTR + bx;
            sm[si]           = v0;
            sm[PSZ + si]     = v1;
            sm[2 * PSZ + si] = v2;
        }
        __syncthreads();

        // ---- sample: warp w handles rows i0 + st*8 + w, lane l = j offset ----
        const float fxj = fx00 + (float)l * djx;
        const float fyj = fy00 + (float)l * djy;

        #pragma unroll
        for (int st = 0; st < 4; st++) {
            const float il = (float)(st * 8 + w);
            const float fx = fxj + il * dix;
            const float fy = fyj + il * diy;
            const float x0f = floorf(fx);
            const float y0f = floorf(fy);
            const float wx1 = fx - x0f, wx0 = 1.f - wx1;
            const float wy1 = fy - y0f, wy0 = 1.f - wy1;
            const int ix = (int)x0f - xlo;        // in [0,46]
            const int iy = (int)y0f - ylo;
            const int base = iy * PSTR + ix;

            const float w00 = wy0 * wx0, w01 = wy0 * wx1;
            const float w10 = wy1 * wx0, w11 = wy1 * wx1;

            #pragma unroll
            for (int ch = 0; ch < 3; ch++) {
                const float* pl = sm + ch * PSZ + base;
                const float p00 = pl[0];
                const float p01 = pl[1];
                const float p10 = pl[PSTR];
                const float p11 = pl[PSTR + 1];
                acc[st][ch] = fmaf(p00, w00,
                              fmaf(p01, w01,
                              fmaf(p10, w10,
                              fmaf(p11, w11, acc[st][ch]))));
            }
        }
    }

    // ---- reduce over the 32 j-lanes and write out ----
    #pragma unroll
    for (int st = 0; st < 4; st++) {
        #pragma unroll
        for (int ch = 0; ch < 3; ch++) {
            float v = acc[st][ch];
            v += __shfl_xor_sync(0xffffffffu, v, 16);
            v += __shfl_xor_sync(0xffffffffu, v, 8);
            v += __shfl_xor_sync(0xffffffffu, v, 4);
            v += __shfl_xor_sync(0xffffffffu, v, 2);
            v += __shfl_xor_sync(0xffffffffu, v, 1);
            if (l == 0) {
                const int i = i0 + st * 8 + w;
                out[((b * CC + ch) * HH + i) * KK + k] = v;
            }
        }
    }
}

extern "C" void kernel_launch(void* const* d_in, const int* in_sizes, int n_in,
                              void* d_out, int out_size)
{
    const float* x = (const float*)d_in[0];       // (2,3,384,384)
    const float* angles = (const float*)d_in[1];  // (2,180)
    float* out = (float*)d_out;                   // (2,3,384,180)
    (void)in_sizes; (void)n_in; (void)out_size;

    dim3 grid(NTI, BB * KK);                      // 12 x 360 = 4320 blocks
    radon_fused_kernel<<<grid, NTHREADS>>>(x, angles, out);
}

// round 3
// speedup vs baseline: 1.1489x; 1.0008x over previous
#include <cuda_runtime.h>
#include <math.h>

// x (2,3,384,384) f32, angles (2,180) f32 -> out (2,3,384,180) f32
// out[b][c][i][k] = sum_j bilinear(x[b,c], rot_k(i,j))
#define BB 2
#define CC 3
#define HH 384
#define WW 384
#define KK 180

#define TI 32
#define TJ 32
#define NTI (HH / TI)   // 12
#define NTJ (WW / TJ)   // 12

#define BOX 48          // bbox of 32x32 rotated tile + 1px guard each side
#define PSTR 49         // odd word stride -> bank-friendly column walks
#define PSZ (BOX * PSTR)

#define NTHREADS 256

__global__ __launch_bounds__(NTHREADS) void radon_fused_kernel(
    const float* __restrict__ x, const float* __restrict__ angles,
    float* __restrict__ out)
{
    __shared__ float sm[3 * PSZ];   // planar: ch0, ch1, ch2  (28.2 KB)

    const int ti = blockIdx.x;
    const int bk = blockIdx.y;        // b*KK + k
    const int b  = bk / KK;
    const int k  = bk - b * KK;
    const int i0 = ti * TI;

    const float theta = angles[bk] * (float)(M_PI / 180.0);
    float s, c;
    sincosf(theta, &s, &c);

    const float HC = 0.5f * (HH - 1);             // 191.5
    const float dix = s, djx = c;                  // d(fx)/di, d(fx)/dj
    const float diy = c, djy = -s;                 // d(fy)/di, d(fy)/dj

    const float* __restrict__ xb = x + (size_t)b * CC * HH * WW;
    const int HW = HH * WW;

    const int w = threadIdx.x >> 5;   // warp 0..7 -> i row within group
    const int l = threadIdx.x & 31;   // lane -> j within tile

    float acc[4][3];
    #pragma unroll
    for (int st = 0; st < 4; st++)
        #pragma unroll
        for (int ch = 0; ch < 3; ch++) acc[st][ch] = 0.f;

    for (int tj = 0; tj < NTJ; tj++) {
        const int j0 = tj * TJ;
        const float fx00 = HC + ((float)i0 - HC) * s + ((float)j0 - HC) * c;
        const float fy00 = HC + ((float)i0 - HC) * c - ((float)j0 - HC) * s;

        // tile is affine in (i,j): extremes at the 4 corners
        const float eI = (float)(TI - 1), eJ = (float)(TJ - 1);
        const float fxm = fminf(fminf(fx00, fx00 + eI * dix),
                                fminf(fx00 + eJ * djx, fx00 + eI * dix + eJ * djx));
        const float fym = fminf(fminf(fy00, fy00 + eI * diy),
                                fminf(fy00 + eJ * djy, fy00 + eI * diy + eJ * djy));
        const int xlo = (int)floorf(fxm) - 1;
        const int ylo = (int)floorf(fym) - 1;

        __syncthreads();   // previous tile's reads done before overwrite

        // ---- stage 48x48 box, planar, zero-filled outside image ----
        #pragma unroll
        for (int it = 0; it < (BOX * BOX) / NTHREADS; it++) {
            const int p  = threadIdx.x + it * NTHREADS;
            const int by = p / BOX;
            const int bx = p - by * BOX;
            const int gy = ylo + by;
            const int gx = xlo + bx;
            float v0 = 0.f, v1 = 0.f, v2 = 0.f;
            if ((unsigned)gy < (unsigned)HH && (unsigned)gx < (unsigned)WW) {
                const int o = gy * WW + gx;
                v0 = xb[o];
                v1 = xb[HW + o];
                v2 = xb[2 * HW + o];
            }
            const int si = by * PSTR + bx;
            sm[si]           = v0;
            sm[PSZ + si]     = v1;
            sm[2 * PSZ + si] = v2;
        }
        __syncthreads();

        // ---- sample: warp w handles rows i0 + st*8 + w, lane l = j offset ----
        const float fxj = fx00 + (float)l * djx;
        const float fyj = fy00 + (float)l * djy;

        #pragma unroll
        for (int st = 0; st < 4; st++) {
            const float il = (float)(st * 8 + w);
            const float fx = fxj + il * dix;
            const float fy = fyj + il * diy;
            const float x0f = floorf(fx);
            const float y0f = floorf(fy);
            const float wx1 = fx - x0f, wx0 = 1.f - wx1;
            const float wy1 = fy - y0f, wy0 = 1.f - wy1;
            const int ix = (int)x0f - xlo;        // in [0,46]
            const int iy = (int)y0f - ylo;
            const int base = iy * PSTR + ix;

            const float w00 = wy0 * wx0, w01 = wy0 * wx1;
            const float w10 = wy1 * wx0, w11 = wy1 * wx1;

            #pragma unroll
            for (int ch = 0; ch < 3; ch++) {
                const float* pl = sm + ch * PSZ + base;
                const float p00 = pl[0];
                const float p01 = pl[1];
                const float p10 = pl[PSTR];
                const float p11 = pl[PSTR + 1];
                acc[st][ch] = fmaf(p00, w00,
                              fmaf(p01, w01,
                              fmaf(p10, w10,
                              fmaf(p11, w11, acc[st][ch]))));
            }
        }
    }

    // ---- reduce over the 32 j-lanes and write out ----
    #pragma unroll
    for (int st = 0; st < 4; st++) {
        #pragma unroll
        for (int ch = 0; ch < 3; ch++) {
            float v = acc[st][ch];
            v += __shfl_xor_sync(0xffffffffu, v, 16);
            v += __shfl_xor_sync(0xffffffffu, v, 8);
            v += __shfl_xor_sync(0xffffffffu, v, 4);
            v += __shfl_xor_sync(0xffffffffu, v, 2);
            v += __shfl_xor_sync(0xffffffffu, v, 1);
            if (l == 0) {
                const int i = i0 + st * 8 + w;
                out[((b * CC + ch) * HH + i) * KK + k] = v;
            }
        }
    }
}

extern "C" void kernel_launch(void* const* d_in, const int* in_sizes, int n_in,
                              void* d_out, int out_size)
{
    const float* x = (const float*)d_in[0];       // (2,3,384,384)
    const float* angles = (const float*)d_in[1];  // (2,180)
    float* out = (float*)d_out;                   // (2,3,384,180)
    (void)in_sizes; (void)n_in; (void)out_size;

    dim3 grid(NTI, BB * KK);                      // 12 x 360 = 4320 blocks
    radon_fused_kernel<<<grid, NTHREADS>>>(x, angles, out);
}